// round 1
// baseline (speedup 1.0000x reference)
#include <cuda_runtime.h>
#include <math.h>

#define Bb 4
#define Ss 4096
#define Hh 2048
#define Mm 128
#define CH 64
#define NC 64
#define NSLOTS 64
#define NTOK (Bb*Ss)   // 16384

// ---------------- scratch (static device globals; no allocation) ----------------
__device__ float g_q[NTOK*Mm];
__device__ float g_k[NTOK*Mm];
__device__ float g_v[NTOK*Mm];
__device__ float g_w[NTOK];
__device__ float g_r[NTOK*Mm];
__device__ float g_Kagg[NSLOTS*Mm];
__device__ float g_Vagg[NSLOTS*Mm];
__device__ float g_ws[NSLOTS];

// ---------------- canonical 128x128x8 fp32 GEMM body (C = A[M,K] @ Bm[N,K]^T) ----------------
__device__ __forceinline__ void sgemm_body(const float* __restrict__ A,
                                           const float* __restrict__ Bm,
                                           float* __restrict__ C,
                                           int K, int N)
{
    __shared__ __align__(16) float As[8][128];
    __shared__ __align__(16) float Bs[8][128];
    int tid = threadIdx.x;
    int m0 = blockIdx.x * 128;
    int n0 = blockIdx.y * 128;
    int lrow = tid >> 1;
    int lk = (tid & 1) << 2;
    const float* Ap = A + (size_t)(m0 + lrow) * K + lk;
    const float* Bp = Bm + (size_t)(n0 + lrow) * K + lk;
    int tx = tid & 15, ty = tid >> 4;

    float acc[8][8];
#pragma unroll
    for (int i = 0; i < 8; i++)
#pragma unroll
        for (int j = 0; j < 8; j++) acc[i][j] = 0.f;

    for (int k0 = 0; k0 < K; k0 += 8) {
        float4 av = *(const float4*)(Ap + k0);
        float4 bv = *(const float4*)(Bp + k0);
        __syncthreads();
        As[lk + 0][lrow] = av.x; As[lk + 1][lrow] = av.y;
        As[lk + 2][lrow] = av.z; As[lk + 3][lrow] = av.w;
        Bs[lk + 0][lrow] = bv.x; Bs[lk + 1][lrow] = bv.y;
        Bs[lk + 2][lrow] = bv.z; Bs[lk + 3][lrow] = bv.w;
        __syncthreads();
#pragma unroll
        for (int kk = 0; kk < 8; kk++) {
            float a[8], b[8];
            *(float4*)(a)     = *(const float4*)&As[kk][ty * 4];
            *(float4*)(a + 4) = *(const float4*)&As[kk][64 + ty * 4];
            *(float4*)(b)     = *(const float4*)&Bs[kk][tx * 4];
            *(float4*)(b + 4) = *(const float4*)&Bs[kk][64 + tx * 4];
#pragma unroll
            for (int i = 0; i < 8; i++)
#pragma unroll
                for (int j = 0; j < 8; j++)
                    acc[i][j] += a[i] * b[j];
        }
    }
#pragma unroll
    for (int i = 0; i < 8; i++) {
        int r = m0 + ((i < 4) ? (ty * 4 + i) : (64 + ty * 4 + (i - 4)));
        float* Cr = C + (size_t)r * N + n0;
        *(float4*)(Cr + tx * 4)      = make_float4(acc[i][0], acc[i][1], acc[i][2], acc[i][3]);
        *(float4*)(Cr + 64 + tx * 4) = make_float4(acc[i][4], acc[i][5], acc[i][6], acc[i][7]);
    }
}

__global__ void __launch_bounds__(256) sgemm_nt(const float* __restrict__ A,
                                                const float* __restrict__ Bm,
                                                float* __restrict__ C, int K, int N)
{
    sgemm_body(A, Bm, C, K, N);
}

// fused q/k/v projections via blockIdx.z for better occupancy (384 blocks)
__global__ void __launch_bounds__(256) proj_gemm(const float* __restrict__ x,
                                                 const float* __restrict__ Wq,
                                                 const float* __restrict__ Wk,
                                                 const float* __restrict__ Wv)
{
    const float* W; float* C;
    if (blockIdx.z == 0)      { W = Wq; C = g_q; }
    else if (blockIdx.z == 1) { W = Wk; C = g_k; }
    else                      { W = Wv; C = g_v; }
    sgemm_body(x, W, C, Hh, Mm);
}

// ---------------- gate: w[t] = sigmoid(x_t . Wg + b) ----------------
__global__ void __launch_bounds__(256) gate_kernel(const float* __restrict__ x,
                                                   const float* __restrict__ Wg,
                                                   const float* __restrict__ gb)
{
    int gwarp = (blockIdx.x * 256 + threadIdx.x) >> 5;
    int lane = threadIdx.x & 31;
    if (gwarp >= NTOK) return;
    const float4* x4 = (const float4*)(x + (size_t)gwarp * Hh);
    const float4* w4 = (const float4*)Wg;
    float s = 0.f;
    for (int d = lane; d < Hh / 4; d += 32) {
        float4 a = x4[d], b = w4[d];
        s += a.x * b.x + a.y * b.y + a.z * b.z + a.w * b.w;
    }
#pragma unroll
    for (int o = 16; o; o >>= 1) s += __shfl_xor_sync(0xffffffffu, s, o);
    if (lane == 0) g_w[gwarp] = 1.f / (1.f + expf(-(s + gb[0])));
}

// ---------------- per-chunk aggregates: k_agg, v_agg, write_str ----------------
__global__ void __launch_bounds__(256) agg_kernel()
{
    int i = blockIdx.x;     // chunk
    int tid = threadIdx.x;  // 256 = one thread per (b,c) token in phase 1
    __shared__ float sw[256];
    __shared__ float sik[256];
    __shared__ float siv[256];
    __shared__ float red[256];
    {
        int b = tid >> 6, c = tid & 63;
        size_t t = (size_t)b * Ss + (size_t)i * CH + c;
        const float* kr = g_k + t * Mm;
        const float* vr = g_v + t * Mm;
        float nk = 0.f, nv = 0.f;
        for (int d = 0; d < Mm; d++) {
            float a = kr[d]; nk += a * a;
            float u = vr[d]; nv += u * u;
        }
        sik[tid] = 1.f / fmaxf(sqrtf(nk), 1e-12f);
        siv[tid] = 1.f / fmaxf(sqrtf(nv), 1e-12f);
        float wv = g_w[t];
        sw[tid] = wv;
        red[tid] = wv;
    }
    __syncthreads();
    for (int o = 128; o; o >>= 1) { if (tid < o) red[tid] += red[tid + o]; __syncthreads(); }
    float sumw = red[0];
    float wsum = fmaxf(sumw, 1e-8f);
    __syncthreads();

    // phase 2: threads 0..127 accumulate k dims, 128..255 accumulate v dims (coalesced)
    int d = tid & 127;
    bool isv = (tid >= 128);
    const float* src = isv ? g_v : g_k;
    const float* inv = isv ? siv : sik;
    float acc = 0.f;
    for (int j = 0; j < 256; j++) {
        int b = j >> 6, c = j & 63;
        size_t tj = (size_t)b * Ss + (size_t)i * CH + c;
        acc += sw[j] * inv[j] * src[tj * Mm + d];
    }
    float mean = acc / wsum;
    red[tid] = mean * mean;
    __syncthreads();
    for (int o = 64; o; o >>= 1) { if ((tid & 127) < o) red[tid] += red[tid + o]; __syncthreads(); }
    float nrm = fmaxf(sqrtf(red[isv ? 128 : 0]), 1e-12f);
    float outv = mean / nrm;
    if (isv) g_Vagg[i * Mm + d] = outv;
    else     g_Kagg[i * Mm + d] = outv;
    if (tid == 0) g_ws[i] = sumw * (1.f / 256.f);
}

// ---------------- mean write strength ----------------
__global__ void meanws_kernel(float* __restrict__ out, int out_size)
{
    if (threadIdx.x == 0 && out_size > NTOK * Hh) {
        float s = 0.f;
        for (int j = 0; j < NC; j++) s += g_ws[j];
        out[(size_t)NTOK * Hh] = s / (float)NC;
    }
}

// ---------------- attention read: r_t = softmax(beta q_t . Kagg[active]) @ Vagg ----------------
// grid (chunk, batch); 256 threads = 8 warps, each warp handles 8 tokens.
__global__ void __launch_bounds__(256) attn_kernel(const float* __restrict__ log_beta,
                                                   float* __restrict__ r_out)
{
    extern __shared__ float sm[];
    float* ksm = sm;              // 64*129
    float* vsm = ksm + 64 * 129;  // 64*129
    float* qsm = vsm + 64 * 129;  // 64*129
    float* psm = qsm + 64 * 129;  // 8*64
    __shared__ float str[64];
    __shared__ float ssum;

    int i = blockIdx.x;   // chunk
    int bb = blockIdx.y;  // batch
    int tid = threadIdx.x;
    float beta = expf(log_beta[0]);

    for (int idx = tid; idx < 64 * 128; idx += 256) {
        int j = idx >> 7, d = idx & 127;
        ksm[j * 129 + d] = g_Kagg[idx];
        vsm[j * 129 + d] = g_Vagg[idx];
    }
    size_t tbase = (size_t)bb * Ss + (size_t)i * CH;
    for (int idx = tid; idx < 64 * 128; idx += 256) {
        int c = idx >> 7, d = idx & 127;
        qsm[c * 129 + d] = g_q[(tbase + c) * Mm + d];
    }
    if (tid < 64) {
        float dc = powf(0.999f, 64.f);
        float s = 0.f;
        if (tid < i) s = g_ws[tid] * powf(dc, (float)(i - 1 - tid));
        str[tid] = s;
    }
    __syncthreads();
    if (tid == 0) {
        float s = 0.f;
        for (int j = 0; j < 64; j++) s += str[j];
        ssum = s;
    }
    __syncthreads();

    bool valid = (ssum >= 1e-8f);
    int w = tid >> 5, lane = tid & 31;
    float m0ok = (str[lane] > 1e-8f)      ? 0.f : -1e9f;
    float m1ok = (str[lane + 32] > 1e-8f) ? 0.f : -1e9f;
    const float* k0 = ksm + lane * 129;
    const float* k1 = ksm + (lane + 32) * 129;

    for (int it = 0; it < 8; it++) {
        int c = w * 8 + it;
        const float* qrow = qsm + c * 129;
        float s0 = 0.f, s1 = 0.f;
#pragma unroll 8
        for (int d = 0; d < 128; d++) {
            float qd = qrow[d];
            s0 += qd * k0[d];
            s1 += qd * k1[d];
        }
        s0 = s0 * beta + m0ok;
        s1 = s1 * beta + m1ok;
        float mx = fmaxf(s0, s1);
#pragma unroll
        for (int o = 16; o; o >>= 1) mx = fmaxf(mx, __shfl_xor_sync(0xffffffffu, mx, o));
        float p0 = expf(s0 - mx);
        float p1 = expf(s1 - mx);
        float sum = p0 + p1;
#pragma unroll
        for (int o = 16; o; o >>= 1) sum += __shfl_xor_sync(0xffffffffu, sum, o);
        float invs = 1.f / sum;
        psm[w * 64 + lane]      = p0 * invs;
        psm[w * 64 + lane + 32] = p1 * invs;
        __syncwarp();
        float a0 = 0.f, a1 = 0.f, a2 = 0.f, a3 = 0.f;
#pragma unroll 4
        for (int j = 0; j < 64; j++) {
            float pj = psm[w * 64 + j];
            const float* vr = vsm + j * 129 + lane;
            a0 += pj * vr[0];
            a1 += pj * vr[32];
            a2 += pj * vr[64];
            a3 += pj * vr[96];
        }
        if (!valid) { a0 = a1 = a2 = a3 = 0.f; }
        float* ro = r_out + (tbase + c) * Mm;
        ro[lane]      = a0;
        ro[lane + 32] = a1;
        ro[lane + 64] = a2;
        ro[lane + 96] = a3;
        __syncwarp();
    }
}

// ---------------- per-token output norm clamp (deterministic, no atomics) ----------------
__global__ void __launch_bounds__(256) norm_kernel(float* __restrict__ out)
{
    __shared__ float red[256];
    size_t t = blockIdx.x;
    float* row = out + t * (size_t)Hh;
    int tid = threadIdx.x;
    float4* r4 = (float4*)row;
    float ss = 0.f;
#pragma unroll
    for (int u = 0; u < 2; u++) {
        float4 v = r4[tid + u * 256];
        ss += v.x * v.x + v.y * v.y + v.z * v.z + v.w * v.w;
    }
    red[tid] = ss;
    __syncthreads();
    for (int o = 128; o; o >>= 1) { if (tid < o) red[tid] += red[tid + o]; __syncthreads(); }
    float nrm = fmaxf(sqrtf(red[0]), 1e-6f);
    float sc = fminf(10.f / nrm, 1.f);
    if (sc < 1.f) {
#pragma unroll
        for (int u = 0; u < 2; u++) {
            float4 v = r4[tid + u * 256];
            v.x *= sc; v.y *= sc; v.z *= sc; v.w *= sc;
            r4[tid + u * 256] = v;
        }
    }
}

// ---------------- launch ----------------
extern "C" void kernel_launch(void* const* d_in, const int* in_sizes, int n_in,
                              void* d_out, int out_size)
{
    const float* x  = (const float*)d_in[0];
    const float* Wq = (const float*)d_in[1];
    const float* Wk = (const float*)d_in[2];
    const float* Wv = (const float*)d_in[3];
    const float* Wo = (const float*)d_in[4];
    const float* Wg = (const float*)d_in[5];
    const float* gb = (const float*)d_in[6];
    const float* lb = (const float*)d_in[7];
    float* out = (float*)d_out;

    float *pr;
    cudaGetSymbolAddress((void**)&pr, g_r);

    const int ATTN_SMEM = (3 * 64 * 129 + 8 * 64) * 4;  // ~99 KB
    cudaFuncSetAttribute(attn_kernel, cudaFuncAttributeMaxDynamicSharedMemorySize, ATTN_SMEM);

    // 1. projections q/k/v (384 blocks)
    proj_gemm<<<dim3(NTOK / 128, 1, 3), 256>>>(x, Wq, Wk, Wv);
    // 2. gate
    gate_kernel<<<NTOK / 8, 256>>>(x, Wg, gb);
    // 3. per-chunk write aggregates
    agg_kernel<<<NC, 256>>>();
    // 4. mean write strength (second output scalar)
    meanws_kernel<<<1, 32>>>(out, out_size);
    // 5. attention reads (fully parallel across chunks)
    attn_kernel<<<dim3(NC, Bb), 256, ATTN_SMEM>>>(lb, pr);
    // 6. output projection
    sgemm_nt<<<dim3(NTOK / 128, Hh / 128), 256>>>(pr, Wo, out, Mm, Hh);
    // 7. norm clamp
    norm_kernel<<<NTOK, 256>>>(out);
}